// round 2
// baseline (speedup 1.0000x reference)
#include <cuda_runtime.h>

#define FULL 0xFFFFFFFFu

namespace {
constexpr int BATCH = 256;
constexpr int MAXT  = 512;
constexpr int T1    = MAXT + 1;      // 513
constexpr int S     = 64;
constexpr int NPOS  = BATCH * T1;    // 131328
constexpr int TPOS  = 16;            // positions per CTA in phase 1
constexpr int NCTA1 = NPOS / TPOS;   // 8208 (exact)
}

// Per position: 16 x float4 {asel, beta, omb, start} — 33.6 MB scratch.
__device__ float4 g_mid[NPOS * 16];
__device__ float  g_batch[BATCH];

// ---------------------------------------------------------------------------
// Phase 1: fused GEMV (304 cols) + log-softmax + action gather, 16 pos / CTA.
// Threads 0..255: action cols; 256..287: stop cols; 288..319: start cols.
// ---------------------------------------------------------------------------
__global__ __launch_bounds__(320) void phase1_kernel(
    const float* __restrict__ s_i,
    const int*   __restrict__ actions,
    const int*   __restrict__ lengths,
    const float* __restrict__ Wa, const float* __restrict__ ba,
    const float* __restrict__ Ws, const float* __restrict__ bs,
    const float* __restrict__ Wst, const float* __restrict__ bst)
{
    __shared__ __align__(16) float sh_s[TPOS][S];
    __shared__ __align__(16) float sh_out[TPOS][64];
    __shared__ int sh_act[TPOS];
    __shared__ int sh_skip;

    const int tid  = threadIdx.x;
    const int pos0 = blockIdx.x * TPOS;

    // Dead-tile check (phase 2 never reads t > lengths[b]) + action gather.
    if (tid < 32) {
        int pos = pos0 + (tid & 15);
        int b = pos / T1;
        int t = pos - b * T1;
        bool need = (tid < 16) && (t <= __ldg(&lengths[b]));
        unsigned m = __ballot_sync(FULL, need);
        if (tid == 0) sh_skip = (m == 0) ? 1 : 0;
        if (tid < 16) sh_act[tid] = (t < MAXT) ? __ldg(&actions[b * MAXT + t]) : 0;
    }
    // Stage the s tile: 16 pos x 64 floats = 256 float4, fully coalesced.
    if (tid < 256) {
        ((float4*)sh_s)[tid] = ((const float4*)s_i)[pos0 * (S / 4) + tid];
    }
    __syncthreads();
    if (sh_skip) return;

    // Uniform GEMV loop for all 320 threads (different column pointer/stride).
    const float* wcol;
    int stride;
    float bias;
    if (tid < 256)      { wcol = Wa + tid;           stride = 256; bias = ba[tid]; }
    else if (tid < 288) { wcol = Ws + (tid - 256);   stride = 32;  bias = bs[tid - 256]; }
    else                { int c = (tid - 288) & 15;  wcol = Wst + c; stride = 16; bias = bst[c]; }

    float acc[TPOS];
    #pragma unroll
    for (int p = 0; p < TPOS; p++) acc[p] = bias;

    #pragma unroll 4
    for (int s4 = 0; s4 < S; s4 += 4) {
        float w0 = __ldg(&wcol[(s4 + 0) * stride]);
        float w1 = __ldg(&wcol[(s4 + 1) * stride]);
        float w2 = __ldg(&wcol[(s4 + 2) * stride]);
        float w3 = __ldg(&wcol[(s4 + 3) * stride]);
        #pragma unroll
        for (int p = 0; p < TPOS; p++) {
            float4 sv = *(const float4*)&sh_s[p][s4];   // LDS.128 broadcast
            acc[p] = fmaf(sv.w, w3, fmaf(sv.z, w2, fmaf(sv.y, w1, fmaf(sv.x, w0, acc[p]))));
        }
    }

    const int warp = tid >> 5;
    if (warp < 8) {
        // Action log-softmax over 16 lanes per block; gather selected action.
        int a  = tid & 15;
        int nb = (tid >> 4) & 15;
        #pragma unroll 2
        for (int p = 0; p < TPOS; p++) {
            float z = acc[p];
            float m = z;
            #pragma unroll
            for (int d = 8; d; d >>= 1) m = fmaxf(m, __shfl_xor_sync(FULL, m, d));
            float e = __expf(z - m);
            #pragma unroll
            for (int d = 8; d; d >>= 1) e += __shfl_xor_sync(FULL, e, d);
            float lse = m + __logf(e);
            if (a == sh_act[p]) sh_out[p][nb * 4 + 0] = z - lse;   // asel
        }
    } else if (warp == 8) {
        // Stop log-softmax over pairs: even lane = STOP (beta), odd = CONTINUE (omb).
        int c = tid - 256, nb = c >> 1, ix = c & 1;
        #pragma unroll 2
        for (int p = 0; p < TPOS; p++) {
            float z = acc[p];
            float o = __shfl_xor_sync(FULL, z, 1);
            float m = fmaxf(z, o);
            float l = m + __logf(__expf(z - m) + __expf(o - m));
            sh_out[p][nb * 4 + 1 + ix] = z - l;                    // beta / omb
        }
    } else {
        // Start log-softmax over 16 lanes (lanes 16..31 duplicate, no write).
        int c = (tid - 288) & 15;
        #pragma unroll 2
        for (int p = 0; p < TPOS; p++) {
            float z = acc[p];
            float m = z;
            #pragma unroll
            for (int d = 8; d; d >>= 1) m = fmaxf(m, __shfl_xor_sync(FULL, m, d));
            float e = __expf(z - m);
            #pragma unroll
            for (int d = 8; d; d >>= 1) e += __shfl_xor_sync(FULL, e, d);
            float lse = m + __logf(e);
            if (tid < 304) sh_out[p][c * 4 + 3] = z - lse;         // start
        }
    }
    __syncthreads();

    // Vectorized, coalesced flush of the staged tile.
    if (tid < 256) {
        g_mid[pos0 * 16 + tid] = ((const float4*)sh_out)[tid];
    }
}

// ---------------------------------------------------------------------------
// Phase 2: serial HMM recursion, one warp per batch element.
// Lanes 0..15 hold the 16 states (lanes 16..31 mirror so FULL-mask shfl works).
// f is recentred with each step's own LSE (recursion is shift-invariant),
// eliminating the max-reduction from the critical chain.
// ---------------------------------------------------------------------------
__global__ __launch_bounds__(32) void phase2_kernel(const int* __restrict__ lengths)
{
    const int b    = blockIdx.x;
    const int lane = threadIdx.x;
    const int j    = lane & 15;

    const float4* mid = g_mid + (size_t)b * T1 * 16 + j;
    const int L = __ldg(&lengths[b]);         // 1..512

    float4 v0 = *mid;
    float f = v0.w + v0.x;                    // start[0] + asel[0]
    float C = 0.0f;                           // accumulated recentring offset
    const float4* p = mid + 16;
    float4 nxt = *p;                          // prefetch t=1 (always valid)

    for (int t = 1; t < L; t++) {
        float4 v = nxt;
        p += 16;
        nxt = *p;                             // t+1 <= L <= 512 < T1, valid

        // lse = logsumexp_k(f_k + beta_k); f is centred so no max needed.
        float e = __expf(f + v.y);
        #pragma unroll
        for (int d = 8; d; d >>= 1) e += __shfl_xor_sync(FULL, e, d);
        float lse = __logf(e);

        // f' = logaddexp(f + omb - lse, start) + asel   (relative to C += lse)
        float a1 = f + v.z - lse;
        float a2 = v.w;
        float mx = fmaxf(a1, a2);
        f = mx + __logf(__expf(a1 - mx) + __expf(a2 - mx)) + v.x;
        C += lse;
    }

    // After the loop, nxt holds position t = L (holds for L == 1 too).
    float4 vL = nxt;
    float e = __expf(f + vL.y);               // x0 + x1 (beta at t = L)
    #pragma unroll
    for (int d = 8; d; d >>= 1) e += __shfl_xor_sync(FULL, e, d);
    if (lane == 0) g_batch[b] = C + __logf(e);
}

// ---------------------------------------------------------------------------
// Phase 3: deterministic fixed-order reduction of 256 per-batch terms.
// ---------------------------------------------------------------------------
__global__ __launch_bounds__(256) void finalize_kernel(float* __restrict__ out)
{
    __shared__ float sh[BATCH];
    int t = threadIdx.x;
    sh[t] = g_batch[t];
    __syncthreads();
    #pragma unroll
    for (int s = 128; s > 0; s >>= 1) {
        if (t < s) sh[t] += sh[t + s];
        __syncthreads();
    }
    if (t == 0) out[0] = -sh[0];
}

// ---------------------------------------------------------------------------
// d_in order: s_i_batch, actions_batch, lengths, W_action, b_action,
//             W_stop, b_stop, W_start, b_start
// ---------------------------------------------------------------------------
extern "C" void kernel_launch(void* const* d_in, const int* in_sizes, int n_in,
                              void* d_out, int out_size)
{
    const float* s_i     = (const float*)d_in[0];
    const int*   actions = (const int*)d_in[1];
    const int*   lengths = (const int*)d_in[2];
    const float* Wa      = (const float*)d_in[3];
    const float* ba      = (const float*)d_in[4];
    const float* Ws      = (const float*)d_in[5];
    const float* bs      = (const float*)d_in[6];
    const float* Wst     = (const float*)d_in[7];
    const float* bst     = (const float*)d_in[8];

    phase1_kernel<<<NCTA1, 320>>>(s_i, actions, lengths, Wa, ba, Ws, bs, Wst, bst);
    phase2_kernel<<<BATCH, 32>>>(lengths);
    finalize_kernel<<<1, BATCH>>>((float*)d_out);
}